// round 2
// baseline (speedup 1.0000x reference)
#include <cuda_runtime.h>
#include <math.h>

#define NN 50000
#define NE 800000
#define NG 64
#define NC 10

// ---------------- scratch (static device globals; no runtime alloc) --------
__device__ __align__(16) float g_dinv[NN];
__device__ int   g_cnt[NN];
__device__ int   g_rowptr[NN + 1];
__device__ int   g_cursor[NN];
__device__ int   g_col[NE];
__device__ float g_val[NE];
__device__ __align__(16) float g_bufA[NN * 256];
__device__ __align__(16) float g_bufB[NN * 256];
__device__ __align__(16) float g_bufT[NN * 128];
__device__ float g_pool[NG * 256];
__device__ float g_gcnt[NG];

// ---------------- preprocessing kernels ------------------------------------
__global__ void zero_kernel() {
    int i = blockIdx.x * blockDim.x + threadIdx.x;
    if (i < NN) g_cnt[i] = 0;
    if (i < NG * 256) g_pool[i] = 0.f;
    if (i < NG) g_gcnt[i] = 0.f;
}

__global__ void count_kernel(const int* __restrict__ ei) {
    int e = blockIdx.x * blockDim.x + threadIdx.x;
    if (e < NE) atomicAdd(&g_cnt[ei[NE + e]], 1);
}

__global__ void dinv_kernel() {
    int i = blockIdx.x * blockDim.x + threadIdx.x;
    if (i < NN) g_dinv[i] = rsqrtf((float)(g_cnt[i] + 1));  // +1 self loop
}

// single-block exclusive scan of g_cnt -> g_rowptr / g_cursor
__global__ void scan_kernel() {
    __shared__ int sdata[1024];
    int tid = threadIdx.x;
    int carry = 0;
    for (int base = 0; base < NN; base += 1024) {
        int i = base + tid;
        int v = (i < NN) ? g_cnt[i] : 0;
        sdata[tid] = v;
        __syncthreads();
        for (int off = 1; off < 1024; off <<= 1) {
            int t = (tid >= off) ? sdata[tid - off] : 0;
            __syncthreads();
            sdata[tid] += t;
            __syncthreads();
        }
        int excl = sdata[tid] - v;
        if (i < NN) { g_rowptr[i] = carry + excl; g_cursor[i] = carry + excl; }
        int total = sdata[1023];
        carry += total;
        __syncthreads();
    }
    if (tid == 0) g_rowptr[NN] = carry;
}

__global__ void fill_kernel(const int* __restrict__ ei) {
    int e = blockIdx.x * blockDim.x + threadIdx.x;
    if (e >= NE) return;
    int s = ei[e];
    int d = ei[NE + e];
    int pos = atomicAdd(&g_cursor[d], 1);
    g_col[pos] = s;
    g_val[pos] = g_dinv[s] * g_dinv[d];
}

// ---------------- aggregation: out[i] = dinv[i]^2*h[i] + sum val*h[col] ----
template <int F>
__global__ void agg_kernel(const float* __restrict__ h, float* __restrict__ out) {
    int node = blockIdx.x * blockDim.y + threadIdx.y;
    if (node >= NN) return;
    int f = threadIdx.x;
    float dv = g_dinv[node];
    float acc = dv * dv * __ldg(&h[node * F + f]);
    int e = g_rowptr[node], end = g_rowptr[node + 1];
    for (; e < end; e++) {
        acc += g_val[e] * __ldg(&h[g_col[e] * F + f]);
    }
    out[node * F + f] = acc;
}

// ---------------- dense: out = relu(in @ W + b) ----------------------------
// 256 threads/block, 4 features x TN nodes per thread, W staged in SMEM.
template <int K, int F, int TN>
__global__ __launch_bounds__(256) void gemm_relu_kernel(
    const float* __restrict__ in, const float* __restrict__ W,
    const float* __restrict__ bias, float* __restrict__ out)
{
    constexpr int TF = 4;
    constexpr int BX = F / TF;
    constexpr int BY = 256 / BX;
    constexpr int NT = TN * BY;
    constexpr int NTILES = (NN + NT - 1) / NT;
    extern __shared__ float smem[];
    float* sW = smem;             // [K][F]
    float* sh = smem + K * F;     // [NT][K]
    int tid = threadIdx.y * BX + threadIdx.x;

    const float4* Wv = (const float4*)W;
    float4* sWv = (float4*)sW;
    for (int i = tid; i < K * F / 4; i += 256) sWv[i] = Wv[i];

    int fq = threadIdx.x;
    float4 bv = ((const float4*)bias)[fq];

    for (int tile = blockIdx.x; tile < NTILES; tile += gridDim.x) {
        int node0 = tile * NT;
        __syncthreads();   // protects sh reuse AND first-use of sW
        for (int i = tid; i < NT * K; i += 256) {
            int j = i / K, k = i - j * K;
            int nd = node0 + j;
            sh[i] = (nd < NN) ? in[nd * K + k] : 0.f;
        }
        __syncthreads();

        float acc[TN][4];
        #pragma unroll
        for (int j = 0; j < TN; j++) {
            acc[j][0] = bv.x; acc[j][1] = bv.y; acc[j][2] = bv.z; acc[j][3] = bv.w;
        }
        const float* shb = sh + threadIdx.y * TN * K;
        #pragma unroll 4
        for (int k = 0; k < K; k++) {
            float4 w = ((const float4*)sW)[k * BX + fq];
            #pragma unroll
            for (int j = 0; j < TN; j++) {
                float hv = shb[j * K + k];
                acc[j][0] += w.x * hv;
                acc[j][1] += w.y * hv;
                acc[j][2] += w.z * hv;
                acc[j][3] += w.w * hv;
            }
        }
        #pragma unroll
        for (int j = 0; j < TN; j++) {
            int node = node0 + threadIdx.y * TN + j;
            if (node < NN) {
                float4 o;
                o.x = fmaxf(acc[j][0], 0.f);
                o.y = fmaxf(acc[j][1], 0.f);
                o.z = fmaxf(acc[j][2], 0.f);
                o.w = fmaxf(acc[j][3], 0.f);
                ((float4*)out)[node * BX + fq] = o;
            }
        }
    }
}

// ---------------- mean-pool pieces -----------------------------------------
__global__ void pool_kernel(const float* __restrict__ h, const int* __restrict__ batch) {
    const int CH = 64;
    int f = threadIdx.x;          // 256
    int n0 = blockIdx.x * CH;
    float acc = 0.f;
    int curg = -1;
    for (int i = 0; i < CH; i++) {
        int nd = n0 + i;
        if (nd >= NN) break;
        int g = batch[nd];
        if (g != curg) {
            if (curg >= 0) atomicAdd(&g_pool[curg * 256 + f], acc);
            acc = 0.f; curg = g;
        }
        acc += h[nd * 256 + f];
    }
    if (curg >= 0) atomicAdd(&g_pool[curg * 256 + f], acc);
}

__global__ void gcnt_kernel(const int* __restrict__ batch) {
    int i = blockIdx.x * blockDim.x + threadIdx.x;
    if (i < NN) atomicAdd(&g_gcnt[batch[i]], 1.f);
}

// ---------------- head: fc + log_softmax -----------------------------------
__global__ void head_kernel(const float* __restrict__ fcW, const float* __restrict__ fcb,
                            float* __restrict__ out) {
    __shared__ float slog[NG * NC];
    int tid = threadIdx.x;
    if (tid < NG * NC) {
        int g = tid / NC, c = tid % NC;
        float inv = 1.f / fmaxf(g_gcnt[g], 1.f);
        float a = fcb[c];
        for (int k = 0; k < 256; k++)
            a += g_pool[g * 256 + k] * inv * fcW[k * NC + c];
        slog[tid] = a;
    }
    __syncthreads();
    if (tid < NG * NC) {
        int g = tid / NC;
        float m = -1e30f;
        for (int i = 0; i < NC; i++) m = fmaxf(m, slog[g * NC + i]);
        float s = 0.f;
        for (int i = 0; i < NC; i++) s += expf(slog[g * NC + i] - m);
        out[tid] = slog[tid] - m - logf(s);
    }
}

// ---------------- launch -----------------------------------------------------
extern "C" void kernel_launch(void* const* d_in, const int* in_sizes, int n_in,
                              void* d_out, int out_size) {
    const float* x   = (const float*)d_in[0];
    const int*   ei  = (const int*)d_in[1];
    const int*   bat = (const int*)d_in[2];
    const float* W1 = (const float*)d_in[3];
    const float* b1 = (const float*)d_in[4];
    const float* W2 = (const float*)d_in[5];
    const float* b2 = (const float*)d_in[6];
    const float* W3 = (const float*)d_in[7];
    const float* b3 = (const float*)d_in[8];
    const float* W4 = (const float*)d_in[9];
    const float* b4 = (const float*)d_in[10];
    const float* fcW = (const float*)d_in[11];
    const float* fcb = (const float*)d_in[12];
    float* out = (float*)d_out;

    float *bufA, *bufB, *bufT;
    cudaGetSymbolAddress((void**)&bufA, g_bufA);
    cudaGetSymbolAddress((void**)&bufB, g_bufB);
    cudaGetSymbolAddress((void**)&bufT, g_bufT);

    // L4 GEMM needs >48KB dynamic SMEM
    cudaFuncSetAttribute(gemm_relu_kernel<128, 256, 4>,
                         cudaFuncAttributeMaxDynamicSharedMemorySize,
                         (128 * 256 + 16 * 128) * 4);

    const int EB = (NE + 255) / 256;
    const int NB = (NN + 255) / 256;

    zero_kernel<<<NB, 256>>>();
    count_kernel<<<EB, 256>>>(ei);
    dinv_kernel<<<NB, 256>>>();
    scan_kernel<<<1, 1024>>>();
    fill_kernel<<<EB, 256>>>(ei);

    // layer 1: agg(x)[5] -> @W1 -> relu -> bufA[32]
    {
        dim3 blk(5, 51);
        agg_kernel<5><<<(NN + 50) / 51, blk>>>(x, bufT);
        int smem = (5 * 32 + 128 * 5) * 4;
        gemm_relu_kernel<5, 32, 4><<<391, dim3(8, 32), smem>>>(bufT, W1, b1, bufA);
    }
    // layer 2: agg(bufA)[32] -> @W2 -> relu -> bufB[64]
    {
        dim3 blk(32, 8);
        agg_kernel<32><<<(NN + 7) / 8, blk>>>(bufA, bufT);
        int smem = (32 * 64 + 64 * 32) * 4;
        gemm_relu_kernel<32, 64, 4><<<592, dim3(16, 16), smem>>>(bufT, W2, b2, bufB);
    }
    // layer 3: agg(bufB)[64] -> @W3 -> relu -> bufA[128]
    {
        dim3 blk(64, 4);
        agg_kernel<64><<<(NN + 3) / 4, blk>>>(bufB, bufT);
        int smem = (64 * 128 + 32 * 64) * 4;
        gemm_relu_kernel<64, 128, 4><<<592, dim3(32, 8), smem>>>(bufT, W3, b3, bufA);
    }
    // layer 4: agg(bufA)[128] -> @W4 -> relu -> bufB[256]
    {
        dim3 blk(128, 2);
        agg_kernel<128><<<(NN + 1) / 2, blk>>>(bufA, bufT);
        int smem = (128 * 256 + 16 * 128) * 4;
        gemm_relu_kernel<128, 256, 4><<<148, dim3(64, 4), smem>>>(bufT, W4, b4, bufB);
    }

    // mean pool + head
    pool_kernel<<<(NN + 63) / 64, 256>>>(bufB, bat);
    gcnt_kernel<<<NB, 256>>>(bat);
    head_kernel<<<1, 640>>>(fcW, fcb, out);

    (void)in_sizes; (void)n_in; (void)out_size;
}

// round 3
// speedup vs baseline: 1.3951x; 1.3951x over previous
#include <cuda_runtime.h>
#include <math.h>

#define NN 50000
#define NE 800000
#define NG 64
#define NC 10
#define CHUNK 1024
#define NCHUNK ((NN + CHUNK - 1) / CHUNK)   // 49

// ---------------- scratch (static device globals; no runtime alloc) --------
__device__ __align__(16) float g_dinv[NN];
__device__ int   g_cnt[NN];
__device__ int   g_rowptr[NN + 1];
__device__ int   g_cursor[NN];
__device__ int   g_col[NE];
__device__ float g_val[NE];
__device__ int   g_chunksum[NCHUNK];
__device__ int   g_chunkoff[NCHUNK];
__device__ __align__(16) float g_bufA[NN * 256];
__device__ __align__(16) float g_bufB[NN * 256];
__device__ __align__(16) float g_bufT[NN * 128];
__device__ float g_pool[NG * 256];
__device__ float g_gcnt[NG];

// ---------------- preprocessing kernels ------------------------------------
__global__ void zero_kernel() {
    int i = blockIdx.x * blockDim.x + threadIdx.x;
    if (i < NN) g_cnt[i] = 0;
    if (i < NG * 256) g_pool[i] = 0.f;
    if (i < NG) g_gcnt[i] = 0.f;
}

__global__ void count_kernel(const int* __restrict__ ei) {
    int e = blockIdx.x * blockDim.x + threadIdx.x;
    if (e < NE) atomicAdd(&g_cnt[ei[NE + e]], 1);
}

// per-chunk sum of g_cnt (+ fused dinv computation)
__global__ void chunkred_kernel() {
    int c = blockIdx.x, tid = threadIdx.x;
    int base = c * CHUNK;
    int s = 0;
    #pragma unroll
    for (int k = 0; k < CHUNK / 256; k++) {
        int idx = base + tid + k * 256;
        if (idx < NN) {
            int v = g_cnt[idx];
            s += v;
            g_dinv[idx] = rsqrtf((float)(v + 1));   // +1 self loop
        }
    }
    for (int off = 16; off; off >>= 1) s += __shfl_down_sync(~0u, s, off);
    __shared__ int sm[8];
    if ((tid & 31) == 0) sm[tid >> 5] = s;
    __syncthreads();
    if (tid < 8) {
        int t = sm[tid];
        for (int off = 4; off; off >>= 1) t += __shfl_down_sync(0xff, t, off);
        if (tid == 0) g_chunksum[c] = t;
    }
}

// exclusive scan of the 49 chunk sums (one block, 64 threads)
__global__ void chunkoff_kernel() {
    int tid = threadIdx.x;
    int lane = tid & 31, w = tid >> 5;
    int v = (tid < NCHUNK) ? g_chunksum[tid] : 0;
    int incl = v;
    for (int off = 1; off < 32; off <<= 1) {
        int t = __shfl_up_sync(~0u, incl, off);
        if (lane >= off) incl += t;
    }
    __shared__ int ws[2];
    if (lane == 31) ws[w] = incl;
    __syncthreads();
    int excl = incl - v + (w == 1 ? ws[0] : 0);
    if (tid < NCHUNK) g_chunkoff[tid] = excl;
}

// per-chunk exclusive scan -> rowptr/cursor
__global__ void chunkscan_kernel() {
    __shared__ int warpsum[32];
    int c = blockIdx.x, tid = threadIdx.x;
    int i = c * CHUNK + tid;
    int v = (i < NN) ? g_cnt[i] : 0;
    int lane = tid & 31, w = tid >> 5;
    int incl = v;
    for (int off = 1; off < 32; off <<= 1) {
        int t = __shfl_up_sync(~0u, incl, off);
        if (lane >= off) incl += t;
    }
    if (lane == 31) warpsum[w] = incl;
    __syncthreads();
    if (w == 0) {
        int ws = warpsum[lane];
        for (int off = 1; off < 32; off <<= 1) {
            int t = __shfl_up_sync(~0u, ws, off);
            if (lane >= off) ws += t;
        }
        warpsum[lane] = ws;
    }
    __syncthreads();
    int excl = incl - v + (w > 0 ? warpsum[w - 1] : 0) + g_chunkoff[c];
    if (i < NN) { g_rowptr[i] = excl; g_cursor[i] = excl; }
    if (i == NN - 1) g_rowptr[NN] = excl + v;
}

__global__ void fill_kernel(const int* __restrict__ ei) {
    int e = blockIdx.x * blockDim.x + threadIdx.x;
    if (e >= NE) return;
    int s = ei[e];
    int d = ei[NE + e];
    int pos = atomicAdd(&g_cursor[d], 1);
    g_col[pos] = s;
    g_val[pos] = g_dinv[s] * g_dinv[d];
}

// ---------------- aggregation ------------------------------------------------
// scalar version (F = 5 only)
template <int F>
__global__ void agg_kernel(const float* __restrict__ h, float* __restrict__ out) {
    int node = blockIdx.x * blockDim.y + threadIdx.y;
    if (node >= NN) return;
    int f = threadIdx.x;
    float dv = g_dinv[node];
    float acc = dv * dv * __ldg(&h[node * F + f]);
    int e = g_rowptr[node], end = g_rowptr[node + 1];
    for (; e < end; e++) {
        acc += g_val[e] * __ldg(&h[g_col[e] * F + f]);
    }
    out[node * F + f] = acc;
}

// float4 version (F % 4 == 0): threads.x = F/4
template <int F>
__global__ void agg4_kernel(const float4* __restrict__ h, float4* __restrict__ out) {
    constexpr int FQ = F / 4;
    int node = blockIdx.x * blockDim.y + threadIdx.y;
    if (node >= NN) return;
    int f = threadIdx.x;
    float dv = g_dinv[node];
    float4 hv = __ldg(&h[node * FQ + f]);
    float s = dv * dv;
    float4 acc = make_float4(s * hv.x, s * hv.y, s * hv.z, s * hv.w);
    int e = g_rowptr[node], end = g_rowptr[node + 1];
    // 2x unrolled edge loop for MLP
    for (; e + 1 < end; e += 2) {
        float w0 = g_val[e],     w1 = g_val[e + 1];
        float4 n0 = __ldg(&h[g_col[e] * FQ + f]);
        float4 n1 = __ldg(&h[g_col[e + 1] * FQ + f]);
        acc.x += w0 * n0.x + w1 * n1.x;
        acc.y += w0 * n0.y + w1 * n1.y;
        acc.z += w0 * n0.z + w1 * n1.z;
        acc.w += w0 * n0.w + w1 * n1.w;
    }
    if (e < end) {
        float w0 = g_val[e];
        float4 n0 = __ldg(&h[g_col[e] * FQ + f]);
        acc.x += w0 * n0.x; acc.y += w0 * n0.y;
        acc.z += w0 * n0.z; acc.w += w0 * n0.w;
    }
    out[node * FQ + f] = acc;
}

// ---------------- dense: out = relu(in @ W + b) ----------------------------
// 256 threads/block, 4 features x TN nodes per thread, W staged in SMEM.
template <int K, int F, int TN>
__global__ __launch_bounds__(256) void gemm_relu_kernel(
    const float* __restrict__ in, const float* __restrict__ W,
    const float* __restrict__ bias, float* __restrict__ out)
{
    constexpr int TF = 4;
    constexpr int BX = F / TF;
    constexpr int BY = 256 / BX;
    constexpr int NT = TN * BY;
    constexpr int NTILES = (NN + NT - 1) / NT;
    extern __shared__ float smem[];
    float* sW = smem;             // [K][F]
    float* sh = smem + K * F;     // [NT][K]
    int tid = threadIdx.y * BX + threadIdx.x;

    const float4* Wv = (const float4*)W;
    float4* sWv = (float4*)sW;
    for (int i = tid; i < K * F / 4; i += 256) sWv[i] = Wv[i];

    int fq = threadIdx.x;
    float4 bv = ((const float4*)bias)[fq];

    for (int tile = blockIdx.x; tile < NTILES; tile += gridDim.x) {
        int node0 = tile * NT;
        __syncthreads();   // protects sh reuse AND first-use of sW
        if constexpr (K % 4 == 0) {
            constexpr int KQ = K / 4;
            const float4* inv4 = (const float4*)in;
            float4* shv = (float4*)sh;
            for (int i = tid; i < NT * KQ; i += 256) {
                int j = i / KQ;
                int nd = node0 + j;
                shv[i] = (nd < NN) ? inv4[nd * KQ + (i - j * KQ)]
                                   : make_float4(0.f, 0.f, 0.f, 0.f);
            }
        } else {
            for (int i = tid; i < NT * K; i += 256) {
                int j = i / K, k = i - j * K;
                int nd = node0 + j;
                sh[i] = (nd < NN) ? in[nd * K + k] : 0.f;
            }
        }
        __syncthreads();

        float acc[TN][4];
        #pragma unroll
        for (int j = 0; j < TN; j++) {
            acc[j][0] = bv.x; acc[j][1] = bv.y; acc[j][2] = bv.z; acc[j][3] = bv.w;
        }
        const float* shb = sh + threadIdx.y * TN * K;
        #pragma unroll 4
        for (int k = 0; k < K; k++) {
            float4 w = ((const float4*)sW)[k * BX + fq];
            #pragma unroll
            for (int j = 0; j < TN; j++) {
                float hv = shb[j * K + k];
                acc[j][0] += w.x * hv;
                acc[j][1] += w.y * hv;
                acc[j][2] += w.z * hv;
                acc[j][3] += w.w * hv;
            }
        }
        #pragma unroll
        for (int j = 0; j < TN; j++) {
            int node = node0 + threadIdx.y * TN + j;
            if (node < NN) {
                float4 o;
                o.x = fmaxf(acc[j][0], 0.f);
                o.y = fmaxf(acc[j][1], 0.f);
                o.z = fmaxf(acc[j][2], 0.f);
                o.w = fmaxf(acc[j][3], 0.f);
                ((float4*)out)[node * BX + fq] = o;
            }
        }
    }
}

// ---------------- mean-pool pieces -----------------------------------------
__global__ void pool_kernel(const float* __restrict__ h, const int* __restrict__ batch) {
    const int CH = 64;
    int f = threadIdx.x;          // 256
    int n0 = blockIdx.x * CH;
    float acc = 0.f;
    int curg = -1;
    for (int i = 0; i < CH; i++) {
        int nd = n0 + i;
        if (nd >= NN) break;
        int g = batch[nd];
        if (g != curg) {
            if (curg >= 0) atomicAdd(&g_pool[curg * 256 + f], acc);
            acc = 0.f; curg = g;
        }
        acc += h[nd * 256 + f];
    }
    if (curg >= 0) atomicAdd(&g_pool[curg * 256 + f], acc);
}

__global__ void gcnt_kernel(const int* __restrict__ batch) {
    int i = blockIdx.x * blockDim.x + threadIdx.x;
    if (i < NN) atomicAdd(&g_gcnt[batch[i]], 1.f);
}

// ---------------- head: fc + log_softmax -----------------------------------
__global__ void head_kernel(const float* __restrict__ fcW, const float* __restrict__ fcb,
                            float* __restrict__ out) {
    __shared__ float slog[NG * NC];
    int tid = threadIdx.x;
    if (tid < NG * NC) {
        int g = tid / NC, c = tid % NC;
        float inv = 1.f / fmaxf(g_gcnt[g], 1.f);
        float a = fcb[c];
        for (int k = 0; k < 256; k++)
            a += g_pool[g * 256 + k] * inv * fcW[k * NC + c];
        slog[tid] = a;
    }
    __syncthreads();
    if (tid < NG * NC) {
        int g = tid / NC;
        float m = -1e30f;
        for (int i = 0; i < NC; i++) m = fmaxf(m, slog[g * NC + i]);
        float s = 0.f;
        for (int i = 0; i < NC; i++) s += expf(slog[g * NC + i] - m);
        out[tid] = slog[tid] - m - logf(s);
    }
}

// ---------------- launch -----------------------------------------------------
extern "C" void kernel_launch(void* const* d_in, const int* in_sizes, int n_in,
                              void* d_out, int out_size) {
    const float* x   = (const float*)d_in[0];
    const int*   ei  = (const int*)d_in[1];
    const int*   bat = (const int*)d_in[2];
    const float* W1 = (const float*)d_in[3];
    const float* b1 = (const float*)d_in[4];
    const float* W2 = (const float*)d_in[5];
    const float* b2 = (const float*)d_in[6];
    const float* W3 = (const float*)d_in[7];
    const float* b3 = (const float*)d_in[8];
    const float* W4 = (const float*)d_in[9];
    const float* b4 = (const float*)d_in[10];
    const float* fcW = (const float*)d_in[11];
    const float* fcb = (const float*)d_in[12];
    float* out = (float*)d_out;

    float *bufA, *bufB, *bufT;
    cudaGetSymbolAddress((void**)&bufA, g_bufA);
    cudaGetSymbolAddress((void**)&bufB, g_bufB);
    cudaGetSymbolAddress((void**)&bufT, g_bufT);

    cudaFuncSetAttribute(gemm_relu_kernel<128, 256, 8>,
                         cudaFuncAttributeMaxDynamicSharedMemorySize,
                         (128 * 256 + 32 * 128) * 4);
    cudaFuncSetAttribute(gemm_relu_kernel<64, 128, 8>,
                         cudaFuncAttributeMaxDynamicSharedMemorySize,
                         (64 * 128 + 64 * 64) * 4);

    const int EB = (NE + 255) / 256;
    const int NB = (NN + 255) / 256;

    zero_kernel<<<NB, 256>>>();
    count_kernel<<<EB, 256>>>(ei);
    chunkred_kernel<<<NCHUNK, 256>>>();
    chunkoff_kernel<<<1, 64>>>();
    chunkscan_kernel<<<NCHUNK, 1024>>>();
    fill_kernel<<<EB, 256>>>(ei);

    // layer 1: agg(x)[5] -> @W1 -> relu -> bufA[32]
    {
        dim3 blk(5, 51);
        agg_kernel<5><<<(NN + 50) / 51, blk>>>(x, bufT);
        int smem = (5 * 32 + 128 * 5) * 4;
        gemm_relu_kernel<5, 32, 4><<<391, dim3(8, 32), smem>>>(bufT, W1, b1, bufA);
    }
    // layer 2: agg(bufA)[32] -> @W2 -> relu -> bufB[64]
    {
        dim3 blk(8, 32);
        agg4_kernel<32><<<(NN + 31) / 32, blk>>>((const float4*)bufA, (float4*)bufT);
        int smem = (32 * 64 + 64 * 32) * 4;
        gemm_relu_kernel<32, 64, 4><<<592, dim3(16, 16), smem>>>(bufT, W2, b2, bufB);
    }
    // layer 3: agg(bufB)[64] -> @W3 -> relu -> bufA[128]
    {
        dim3 blk(16, 16);
        agg4_kernel<64><<<(NN + 15) / 16, blk>>>((const float4*)bufB, (float4*)bufT);
        int smem = (64 * 128 + 64 * 64) * 4;
        gemm_relu_kernel<64, 128, 8><<<592, dim3(32, 8), smem>>>(bufT, W3, b3, bufA);
    }
    // layer 4: agg(bufA)[128] -> @W4 -> relu -> bufB[256]
    {
        dim3 blk(32, 8);
        agg4_kernel<128><<<(NN + 7) / 8, blk>>>((const float4*)bufA, (float4*)bufT);
        int smem = (128 * 256 + 32 * 128) * 4;
        gemm_relu_kernel<128, 256, 8><<<148, dim3(64, 4), smem>>>(bufT, W4, b4, bufB);
    }

    // mean pool + head
    pool_kernel<<<(NN + 63) / 64, 256>>>(bufB, bat);
    gcnt_kernel<<<NB, 256>>>(bat);
    head_kernel<<<1, 640>>>(fcW, fcb, out);

    (void)in_sizes; (void)n_in; (void)out_size;
}